// round 2
// baseline (speedup 1.0000x reference)
#include <cuda_runtime.h>
#include <cuda_bf16.h>
#include <math.h>

// ---------------------------------------------------------------------------
// RPN 3D loss, GB300 (sm_103a)
//
// Pipeline (5 graph-captured kernels on the default stream):
//   k_init   : zero per-gt best trackers + accumulators
//   k_assign : per-anchor IoU vs 32 GTs (division-free), fg/bg flags, argmax GT,
//              and sparse atomicMax candidates for the per-GT best anchor
//   k_force  : apply the best-anchor-per-gt override (last-g-wins, matching
//              scatter ordering)
//   k_loss   : CE over all anchors + smooth-L1 2D/3D regression for FG anchors,
//              block reduction -> double atomics
//   k_final  : normalize and write the scalar loss
//
// NOTE: gt_valid (jnp bool) is delivered as int32 by the harness (only
// float32/int32/bfloat16 exist on the wire) -> read as const int*.
// ---------------------------------------------------------------------------

#define FEAT_H 32
#define FEAT_W 110
#define NA 36
#define NB 8
#define NG 32
#define A_TOTAL (FEAT_H * FEAT_W * NA)   // 126720 (divisible by 256: 495 blocks)
#define STRIDEF 16.0f
#define FG_T 0.5f
#define BEST_T 0.35f

// scratch (device globals: no allocation allowed)
__device__ unsigned long long g_best[NB * NG];   // packed (iou_bits<<32)|(~anchor)
__device__ int g_assign[NB * A_TOTAL];           // agt | fg<<8 | bgcond<<9
__device__ double g_acc[5];                      // ce_sum, n_active, n_fg, l2d, l3d

__global__ void k_init() {
    int t = threadIdx.x;
    if (t < NB * NG) g_best[t] = 0ull;
    if (t < 5) g_acc[t] = 0.0;
}

__global__ __launch_bounds__(256) void k_assign(
    const float* __restrict__ gt_boxes,   // [B,G,4]
    const int*   __restrict__ gt_valid,   // [B,G] (bool as int32)
    const float* __restrict__ anchors)    // [NA,9]
{
    __shared__ float s_gx1[NG], s_gy1[NG], s_gx2[NG], s_gy2[NG], s_ag[NG];
    __shared__ int   s_val[NG];
    __shared__ float s_ax1[NA], s_ay1[NA], s_ax2[NA], s_ay2[NA], s_ar[NA];

    int b = blockIdx.y;
    int t = threadIdx.x;
    if (t < NG) {
        const float* gb = gt_boxes + (b * NG + t) * 4;
        float x1 = gb[0], y1 = gb[1], x2 = gb[2], y2 = gb[3];
        s_gx1[t] = x1; s_gy1[t] = y1; s_gx2[t] = x2; s_gy2[t] = y2;
        s_ag[t] = (x2 - x1 + 1.0f) * (y2 - y1 + 1.0f);
        s_val[t] = (gt_valid[b * NG + t] != 0);
    }
    if (t >= 64 && t < 64 + NA) {
        int n = t - 64;
        const float* an = anchors + n * 9;
        float x1 = an[0], y1 = an[1], x2 = an[2], y2 = an[3];
        s_ax1[n] = x1; s_ay1[n] = y1; s_ax2[n] = x2; s_ay2[n] = y2;
        s_ar[n] = (x2 - x1 + 1.0f) * (y2 - y1 + 1.0f);
    }
    __syncthreads();

    int a  = blockIdx.x * 256 + t;               // always < A_TOTAL
    int na = a % NA;
    int hw = a / NA;
    int wc = hw % FEAT_W;
    int hr = hw / FEAT_W;
    float sx = wc * STRIDEF, sy = hr * STRIDEF;
    float x1 = sx + s_ax1[na], y1 = sy + s_ay1[na];
    float x2 = sx + s_ax2[na], y2 = sy + s_ay2[na];
    float ar = s_ar[na];

    // best iou tracked as rational bestI/bestU (division-free); init = -1/1
    float bestI = -1.0f, bestU = 1.0f;
    int bestG = 0;

    #pragma unroll 8
    for (int g = 0; g < NG; ++g) {
        float iw = fminf(x2, s_gx2[g]) - fmaxf(x1, s_gx1[g]) + 1.0f;
        float ih = fminf(y2, s_gy2[g]) - fmaxf(y1, s_gy1[g]) + 1.0f;
        iw = fmaxf(iw, 0.0f);
        ih = fmaxf(ih, 0.0f);
        float inter = iw * ih;
        float uni   = ar + s_ag[g] - inter;
        bool  v     = (s_val[g] != 0);
        float I = v ? inter : -1.0f;
        float U = v ? uni   : 1.0f;
        // strict >: keeps first maximum (matches jnp.argmax tie-break)
        if (I * bestU > bestI * U) { bestI = I; bestU = U; bestG = g; }
        // sparse candidate for the per-gt best anchor; slightly widened filter
        // (exact iou >= 0.35 test happens in k_force on the divided value)
        if (v && inter >= 0.3489f * uni) {
            float iou = inter / uni;             // same fp32 div as reference
            unsigned long long pk =
                (((unsigned long long)__float_as_uint(iou)) << 32) |
                (unsigned long long)(0xFFFFFFFFu - (unsigned)a);
            atomicMax(&g_best[b * NG + g], pk);
        }
    }

    int fg0 = (bestI + bestI >= bestU) ? 1 : 0;          // iou >= 0.5
    int bgc = (!fg0 && bestI >= 0.0f) ? 1 : 0;           // 0 <= max_ol < 0.5
    g_assign[b * A_TOTAL + a] = bestG | (fg0 << 8) | (bgc << 9);
}

__global__ void k_force(const int* __restrict__ gt_valid) {
    __shared__ int s_force[NB * NG];
    __shared__ int s_ba[NB * NG];
    int t = threadIdx.x;                         // 256 = NB*NG
    unsigned long long pk = g_best[t];
    float iou = __uint_as_float((unsigned)(pk >> 32));
    unsigned ba = 0xFFFFFFFFu - (unsigned)(pk & 0xFFFFFFFFull);
    s_force[t] = (gt_valid[t] != 0) && (iou >= BEST_T);
    s_ba[t] = (int)ba;
    __syncthreads();
    if ((t & 31) == 0) {
        int b = t >> 5;
        // sequential ascending g: duplicate-index scatter -> last g wins
        for (int g = 0; g < NG; ++g) {
            int i = b * NG + g;
            if (s_force[i]) g_assign[b * A_TOTAL + s_ba[i]] = g | 0x100;
        }
    }
}

__device__ __forceinline__ float smooth_l1(float x) {
    float ax = fabsf(x);
    return ax < 1.0f ? 0.5f * ax * ax : ax - 0.5f;
}

__global__ __launch_bounds__(256) void k_loss(
    const float* __restrict__ cls,       // [B,A,4]
    const float* __restrict__ bbox_2d,   // [B,A,4]
    const float* __restrict__ bbox_3d,   // [B,A,7]
    const float* __restrict__ gt_boxes,  // [B,G,4]
    const float* __restrict__ gt_3d,     // [B,G,7]
    const int*   __restrict__ gt_labels, // [B,G]
    const float* __restrict__ anchors,   // [NA,9]
    const float* __restrict__ means,     // [1,11]
    const float* __restrict__ stds)      // [1,11]
{
    __shared__ float s_gtb[NG * 4], s_gt3[NG * 7], s_anc[NA * 9];
    __shared__ float s_mn[11], s_sd[11];
    __shared__ int   s_lbl[NG];
    __shared__ float s_red[8][5];

    int b = blockIdx.y;
    int t = threadIdx.x;
    for (int i = t; i < NG * 4; i += 256) s_gtb[i] = gt_boxes[b * NG * 4 + i];
    for (int i = t; i < NG * 7; i += 256) s_gt3[i] = gt_3d[b * NG * 7 + i];
    for (int i = t; i < NA * 9; i += 256) s_anc[i] = anchors[i];
    if (t < NG) s_lbl[t] = gt_labels[b * NG + t];
    if (t < 11) { s_mn[t] = means[t]; s_sd[t] = stds[t]; }
    __syncthreads();

    int a  = blockIdx.x * 256 + t;
    int pk = g_assign[b * A_TOTAL + a];
    int fg  = (pk >> 8) & 1;
    int bg  = (pk >> 9) & 1;
    int agt = pk & 0xFF;
    int lbl = fg ? s_lbl[agt] : 0;

    const float4 c = reinterpret_cast<const float4*>(cls)[b * A_TOTAL + a];
    float m  = fmaxf(fmaxf(c.x, c.y), fmaxf(c.z, c.w));
    float se = __expf(c.x - m) + __expf(c.y - m) + __expf(c.z - m) + __expf(c.w - m);
    float lse = m + __logf(se);
    float xl = (lbl == 0) ? c.x : (lbl == 1) ? c.y : (lbl == 2) ? c.z : c.w;
    float ce = lse - xl;

    int active = fg | bg;
    float r_ce  = active ? ce : 0.0f;
    float r_act = (float)active;
    float r_fg  = (float)fg;
    float r_l2  = 0.0f, r_l3 = 0.0f;

    if (fg) {
        int na = a % NA;
        int hw = a / NA;
        int wc = hw % FEAT_W;
        int hr = hw / FEAT_W;
        const float* an = s_anc + na * 9;
        float sx = wc * STRIDEF, sy = hr * STRIDEF;
        float x1 = sx + an[0], y1 = sy + an[1];
        float x2 = sx + an[2], y2 = sy + an[3];
        float w  = x2 - x1 + 1.0f, h = y2 - y1 + 1.0f;
        float cx = x1 + 0.5f * w,  cy = y1 + 0.5f * h;

        const float* gb = s_gtb + agt * 4;
        const float* g3 = s_gt3 + agt * 7;
        float gw = gb[2] - gb[0] + 1.0f, gh = gb[3] - gb[1] + 1.0f;
        float gcx = gb[0] + 0.5f * gw,   gcy = gb[1] + 0.5f * gh;

        float t2[4];
        t2[0] = (gcx - cx) / w;
        t2[1] = (gcy - cy) / h;
        t2[2] = logf(gw / w);
        t2[3] = logf(gh / h);
        float t3[7];
        t3[0] = (g3[0] - cx) / w;
        t3[1] = (g3[1] - cy) / h;
        t3[2] = g3[2] - an[4];
        t3[3] = logf(g3[3] / an[5]);
        t3[4] = logf(g3[4] / an[6]);
        t3[5] = logf(g3[5] / an[7]);
        t3[6] = g3[6] - an[8];

        const float4 p2 = reinterpret_cast<const float4*>(bbox_2d)[b * A_TOTAL + a];
        float p2a[4] = {p2.x, p2.y, p2.z, p2.w};
        #pragma unroll
        for (int i = 0; i < 4; ++i) {
            float tv = (t2[i] - s_mn[i]) / s_sd[i];
            r_l2 += smooth_l1(p2a[i] - tv);
        }
        const float* p3 = bbox_3d + (size_t)(b * A_TOTAL + a) * 7;
        #pragma unroll
        for (int i = 0; i < 7; ++i) {
            float tv = (t3[i] - s_mn[4 + i]) / s_sd[4 + i];
            r_l3 += smooth_l1(p3[i] - tv);
        }
    }

    // block reduce 5 values
    float v[5] = {r_ce, r_act, r_fg, r_l2, r_l3};
    #pragma unroll
    for (int i = 0; i < 5; ++i)
        #pragma unroll
        for (int off = 16; off; off >>= 1)
            v[i] += __shfl_down_sync(0xFFFFFFFFu, v[i], off);
    int wid = t >> 5, lane = t & 31;
    if (lane == 0)
        #pragma unroll
        for (int i = 0; i < 5; ++i) s_red[wid][i] = v[i];
    __syncthreads();
    if (wid == 0) {
        float u[5];
        #pragma unroll
        for (int i = 0; i < 5; ++i) u[i] = (lane < 8) ? s_red[lane][i] : 0.0f;
        #pragma unroll
        for (int i = 0; i < 5; ++i)
            #pragma unroll
            for (int off = 4; off; off >>= 1)
                u[i] += __shfl_down_sync(0xFFFFFFFFu, u[i], off);
        if (lane == 0)
            #pragma unroll
            for (int i = 0; i < 5; ++i) atomicAdd(&g_acc[i], (double)u[i]);
    }
}

__global__ void k_final(float* __restrict__ out) {
    double nact = g_acc[1] > 1.0 ? g_acc[1] : 1.0;
    double nfg  = g_acc[2] > 1.0 ? g_acc[2] : 1.0;
    out[0] = (float)(g_acc[0] / nact + g_acc[3] / nfg + g_acc[4] / nfg);
}

extern "C" void kernel_launch(void* const* d_in, const int* in_sizes, int n_in,
                              void* d_out, int out_size) {
    const float* cls  = (const float*)d_in[0];
    const float* b2   = (const float*)d_in[1];
    const float* b3   = (const float*)d_in[2];
    const float* gtb  = (const float*)d_in[3];
    const float* gt3  = (const float*)d_in[4];
    const int*   glbl = (const int*)d_in[5];
    const int*   gval = (const int*)d_in[6];
    const float* anc  = (const float*)d_in[7];
    const float* mn   = (const float*)d_in[8];
    const float* sd   = (const float*)d_in[9];
    float* out = (float*)d_out;

    dim3 grid(A_TOTAL / 256, NB);
    k_init<<<1, 256>>>();
    k_assign<<<grid, 256>>>(gtb, gval, anc);
    k_force<<<1, NB * NG>>>(gval);
    k_loss<<<grid, 256>>>(cls, b2, b3, gtb, gt3, glbl, anc, mn, sd);
    k_final<<<1, 1>>>(out);
}

// round 3
// speedup vs baseline: 1.5003x; 1.5003x over previous
#include <cuda_runtime.h>
#include <cuda_bf16.h>
#include <math.h>

// ---------------------------------------------------------------------------
// RPN 3D loss, GB300 (sm_103a)  — round 3
//
//   k_init   : zero per-gt best trackers + bucketed accumulators
//   k_assign : block = (image, template na, row hr); thread = column wc.
//              ih per gt is block-uniform -> uniform skip of non-overlapping
//              gts. Division-free argmax; IEEE div for the fg threshold
//              (same op as the reference). Sparse atomicMax candidates for
//              the per-gt best anchor.
//   k_force  : best-anchor-per-gt override (exact iou >= 0.35 on divided val)
//   k_loss   : CE (2 MUFU + polynomial exp/log) + smooth-L1 for FG anchors,
//              ballot/popc counts, 64-way bucketed double atomics
//   k_final  : reduce buckets, write scalar loss
//
// gt_valid (jnp bool) arrives as int32.
// ---------------------------------------------------------------------------

#define FEAT_H 32
#define FEAT_W 110
#define NA 36
#define NB 8
#define NG 32
#define A_TOTAL (FEAT_H * FEAT_W * NA)   // 126720 = 495*256
#define STRIDEF 16.0f
#define NBUCKET 64

__device__ unsigned long long g_best[NB * NG];     // packed (iou_bits<<32)|(~anchor)
__device__ int g_assign[NB * A_TOTAL];             // agt | fg<<8 | bg<<9
__device__ double g_acc2[5 * NBUCKET];             // ce, n_act, n_fg, l2, l3

__global__ void k_init() {
    int t = threadIdx.x;                           // 384 threads
    if (t < NB * NG) g_best[t] = 0ull;
    if (t < 5 * NBUCKET) g_acc2[t] = 0.0;
}

// ------------------------------- k_assign ----------------------------------
__global__ __launch_bounds__(128) void k_assign(
    const float* __restrict__ gt_boxes,   // [B,G,4]
    const int*   __restrict__ gt_valid,   // [B,G]
    const float* __restrict__ anchors)    // [NA,9]
{
    __shared__ float s_gx1[NG], s_gx2p[NG], s_ag[NG], s_ih[NG];
    __shared__ int   s_any;

    int b  = blockIdx.y;
    int na = blockIdx.x % NA;
    int hr = blockIdx.x / NA;
    int t  = threadIdx.x;

    const float* an = anchors + na * 9;
    float ax1 = __ldg(an + 0), ay1 = __ldg(an + 1);
    float ax2 = __ldg(an + 2), ay2 = __ldg(an + 3);
    float sy  = hr * STRIDEF;
    float y1  = sy + ay1, y2 = sy + ay2;
    float hgt = y2 - y1 + 1.0f;
    float y2p = y2 + 1.0f;

    if (t < NG) {
        const float* gb = gt_boxes + (b * NG + t) * 4;
        float gx1 = gb[0], gy1 = gb[1], gx2 = gb[2], gy2 = gb[3];
        int v = (gt_valid[b * NG + t] != 0);
        float ih = fminf(y2p, gy2 + 1.0f) - fmaxf(y1, gy1);
        ih = fmaxf(ih, 0.0f);
        s_ih[t]   = v ? ih : 0.0f;               // 0 => skip this gt
        s_gx1[t]  = gx1;
        s_gx2p[t] = gx2 + 1.0f;
        s_ag[t]   = (gx2 - gx1 + 1.0f) * (gy2 - gy1 + 1.0f);
        unsigned bal = __ballot_sync(0xFFFFFFFFu, v);
        if (t == 0) s_any = (bal != 0u);
    }
    __syncthreads();
    if (t >= FEAT_W) return;

    float sx  = t * STRIDEF;
    float x1  = sx + ax1, x2 = sx + ax2;
    float wdt = x2 - x1 + 1.0f;
    float ar  = wdt * hgt;
    float x2p = x2 + 1.0f;

    float bestI = -1.0f, bestU = 1.0f;
    int bestG = 0;
    int a = (hr * FEAT_W + t) * NA + na;
    int gbase = b * NG;

    #pragma unroll 4
    for (int g = 0; g < NG; ++g) {
        float ihg = s_ih[g];
        if (ihg > 0.0f) {                         // uniform across block
            float iw = fminf(x2p, s_gx2p[g]) - fmaxf(x1, s_gx1[g]);
            iw = fmaxf(iw, 0.0f);
            float inter = iw * ihg;
            float uni   = ar + s_ag[g] - inter;
            if (inter * bestU > bestI * uni) { bestI = inter; bestU = uni; bestG = g; }
            if (inter >= 0.3489f * uni) {         // widened filter; exact test in k_force
                float iou = inter / uni;
                unsigned long long pk =
                    (((unsigned long long)__float_as_uint(iou)) << 32) |
                    (unsigned long long)(0xFFFFFFFFu - (unsigned)a);
                atomicMax(&g_best[gbase + g], pk);
            }
        }
    }

    int fg0 = 0;
    if (bestI > 0.0f) fg0 = (bestI / bestU >= 0.5f);   // same IEEE div as reference
    int bgc = (!fg0 && s_any) ? 1 : 0;
    g_assign[b * A_TOTAL + a] = bestG | (fg0 << 8) | (bgc << 9);
}

// ------------------------------- k_force -----------------------------------
__global__ void k_force(const int* __restrict__ gt_valid) {
    __shared__ int s_force[NB * NG];
    __shared__ int s_ba[NB * NG];
    int t = threadIdx.x;                          // 256 = NB*NG
    unsigned long long pk = g_best[t];
    float iou = __uint_as_float((unsigned)(pk >> 32));
    unsigned ba = 0xFFFFFFFFu - (unsigned)(pk & 0xFFFFFFFFull);
    s_force[t] = (gt_valid[t] != 0) && (iou >= 0.35f);
    s_ba[t] = (int)ba;
    __syncthreads();
    if ((t & 31) == 0) {
        int b = t >> 5;
        for (int g = 0; g < NG; ++g) {            // ascending: last-forced-g wins
            int i = b * NG + g;
            if (s_force[i]) g_assign[b * A_TOTAL + s_ba[i]] = g | 0x100;
        }
    }
}

// ---------------------- fast transcendental helpers -------------------------
__device__ __forceinline__ float fast_exp_neg(float x) {   // e^x, x <= 0
    float y = x * 1.44269504f;                    // log2(e)
    y = fmaxf(y, -120.0f);
    float fi = y + 12582912.0f;                   // 1.5*2^23: round-to-nearest int
    int   n  = __float_as_int(fi) - 0x4B400000;
    float f  = y - (fi - 12582912.0f);            // [-0.5, 0.5]
    float g  = f * 0.69314718f;
    float p  = 1.0f / 720.0f;
    p = fmaf(p, g, 1.0f / 120.0f);
    p = fmaf(p, g, 1.0f / 24.0f);
    p = fmaf(p, g, 1.0f / 6.0f);
    p = fmaf(p, g, 0.5f);
    p = fmaf(p, g, 1.0f);
    p = fmaf(p, g, 1.0f);
    return __int_as_float(__float_as_int(p) + (n << 23));
}

__device__ __forceinline__ float fast_log14(float x) {     // ln(x), x in [1,4]
    int bits = __float_as_int(x);
    int e = (bits >> 23) - 127;
    float mant = __int_as_float((bits & 0x007FFFFF) | 0x3F800000);  // [1,2)
    if (mant > 1.4142136f) { mant *= 0.5f; e += 1; }
    float u = mant - 1.0f;                        // [-0.2929, 0.4143]
    float q = -1.0f / 12.0f;                      // Taylor ln(1+u), deg 12
    q = fmaf(q, u,  1.0f / 11.0f);
    q = fmaf(q, u, -1.0f / 10.0f);
    q = fmaf(q, u,  1.0f / 9.0f);
    q = fmaf(q, u, -1.0f / 8.0f);
    q = fmaf(q, u,  1.0f / 7.0f);
    q = fmaf(q, u, -1.0f / 6.0f);
    q = fmaf(q, u,  1.0f / 5.0f);
    q = fmaf(q, u, -0.25f);
    q = fmaf(q, u,  1.0f / 3.0f);
    q = fmaf(q, u, -0.5f);
    q = fmaf(q, u,  1.0f);
    return fmaf((float)e, 0.69314718f, u * q);
}

__device__ __forceinline__ float smooth_l1(float x) {
    float ax = fabsf(x);
    return ax < 1.0f ? 0.5f * ax * ax : ax - 0.5f;
}

// ------------------------------- k_loss ------------------------------------
__global__ __launch_bounds__(256) void k_loss(
    const float* __restrict__ cls,       // [B,A,4]
    const float* __restrict__ bbox_2d,   // [B,A,4]
    const float* __restrict__ bbox_3d,   // [B,A,7]
    const float* __restrict__ gt_boxes,  // [B,G,4]
    const float* __restrict__ gt_3d,     // [B,G,7]
    const int*   __restrict__ gt_labels, // [B,G]
    const float* __restrict__ anchors,   // [NA,9]
    const float* __restrict__ means,     // [1,11]
    const float* __restrict__ stds)      // [1,11]
{
    __shared__ float s_red[8][5];
    int b = blockIdx.y;
    int t = threadIdx.x;
    int a = blockIdx.x * 256 + t;

    int pk  = g_assign[b * A_TOTAL + a];
    int fg  = (pk >> 8) & 1;
    int bg  = (pk >> 9) & 1;
    int agt = pk & 0xFF;
    int active = fg | bg;

    const float4 c = __ldg(reinterpret_cast<const float4*>(cls) + b * A_TOTAL + a);
    // pairwise log-sum-exp: 2 MUFU exps + poly exp + poly log
    float m01 = fmaxf(c.x, c.y), n01 = fminf(c.x, c.y);
    float m23 = fmaxf(c.z, c.w), n23 = fminf(c.z, c.w);
    float m   = fmaxf(m01, m23);
    float e01 = __expf(n01 - m01);
    float e23 = __expf(n23 - m23);
    float ed  = fast_exp_neg(-fabsf(m01 - m23));
    bool  g01 = (m01 >= m23);
    float se  = (1.0f + e01) * (g01 ? 1.0f : ed) + (1.0f + e23) * (g01 ? ed : 1.0f);
    float lse = m + fast_log14(se);

    int lbl = fg ? __ldg(&gt_labels[b * NG + agt]) : 0;
    float xl = (lbl == 0) ? c.x : (lbl == 1) ? c.y : (lbl == 2) ? c.z : c.w;
    float r_ce = active ? (lse - xl) : 0.0f;
    float r_l2 = 0.0f, r_l3 = 0.0f;

    if (fg) {
        int na = a % NA;
        int hw = a / NA;
        int wc = hw % FEAT_W;
        int hr = hw / FEAT_W;
        const float* an = anchors + na * 9;
        float sx = wc * STRIDEF, sy = hr * STRIDEF;
        float x1 = sx + __ldg(an + 0), y1 = sy + __ldg(an + 1);
        float x2 = sx + __ldg(an + 2), y2 = sy + __ldg(an + 3);
        float w  = x2 - x1 + 1.0f, h = y2 - y1 + 1.0f;
        float cx = x1 + 0.5f * w,  cy = y1 + 0.5f * h;

        const float* gb = gt_boxes + (b * NG + agt) * 4;
        const float* g3 = gt_3d + (b * NG + agt) * 7;
        float gw = __ldg(gb + 2) - __ldg(gb + 0) + 1.0f;
        float gh = __ldg(gb + 3) - __ldg(gb + 1) + 1.0f;
        float gcx = __ldg(gb + 0) + 0.5f * gw;
        float gcy = __ldg(gb + 1) + 0.5f * gh;

        float t2[4], t3[7];
        t2[0] = (gcx - cx) / w;
        t2[1] = (gcy - cy) / h;
        t2[2] = logf(gw / w);
        t2[3] = logf(gh / h);
        t3[0] = (__ldg(g3 + 0) - cx) / w;
        t3[1] = (__ldg(g3 + 1) - cy) / h;
        t3[2] = __ldg(g3 + 2) - __ldg(an + 4);
        t3[3] = logf(__ldg(g3 + 3) / __ldg(an + 5));
        t3[4] = logf(__ldg(g3 + 4) / __ldg(an + 6));
        t3[5] = logf(__ldg(g3 + 5) / __ldg(an + 7));
        t3[6] = __ldg(g3 + 6) - __ldg(an + 8);

        const float4 p2 = __ldg(reinterpret_cast<const float4*>(bbox_2d) + b * A_TOTAL + a);
        float p2a[4] = {p2.x, p2.y, p2.z, p2.w};
        #pragma unroll
        for (int i = 0; i < 4; ++i) {
            float tv = (t2[i] - __ldg(&means[i])) / __ldg(&stds[i]);
            r_l2 += smooth_l1(p2a[i] - tv);
        }
        const float* p3 = bbox_3d + (size_t)(b * A_TOTAL + a) * 7;
        #pragma unroll
        for (int i = 0; i < 7; ++i) {
            float tv = (t3[i] - __ldg(&means[4 + i])) / __ldg(&stds[4 + i]);
            r_l3 += smooth_l1(__ldg(p3 + i) - tv);
        }
    }

    // warp reduction: ce tree always; counts via ballot/popc; l2/l3 only if warp has fg
    unsigned ba_act = __ballot_sync(0xFFFFFFFFu, active);
    unsigned ba_fg  = __ballot_sync(0xFFFFFFFFu, fg);
    #pragma unroll
    for (int off = 16; off; off >>= 1)
        r_ce += __shfl_down_sync(0xFFFFFFFFu, r_ce, off);
    if (ba_fg) {
        #pragma unroll
        for (int off = 16; off; off >>= 1) {
            r_l2 += __shfl_down_sync(0xFFFFFFFFu, r_l2, off);
            r_l3 += __shfl_down_sync(0xFFFFFFFFu, r_l3, off);
        }
    }
    int wid = t >> 5, lane = t & 31;
    if (lane == 0) {
        s_red[wid][0] = r_ce;
        s_red[wid][1] = (float)__popc(ba_act);
        s_red[wid][2] = (float)__popc(ba_fg);
        s_red[wid][3] = r_l2;
        s_red[wid][4] = r_l3;
    }
    __syncthreads();
    if (wid == 0) {
        float u[5];
        #pragma unroll
        for (int i = 0; i < 5; ++i) u[i] = (lane < 8) ? s_red[lane][i] : 0.0f;
        #pragma unroll
        for (int i = 0; i < 5; ++i)
            #pragma unroll
            for (int off = 4; off; off >>= 1)
                u[i] += __shfl_down_sync(0xFFFFFFFFu, u[i], off);
        if (lane == 0) {
            int bucket = (blockIdx.x + blockIdx.y * 8) & (NBUCKET - 1);
            #pragma unroll
            for (int i = 0; i < 5; ++i)
                atomicAdd(&g_acc2[i * NBUCKET + bucket], (double)u[i]);
        }
    }
}

// ------------------------------- k_final -----------------------------------
__global__ void k_final(float* __restrict__ out) {
    int l = threadIdx.x;                          // 32 threads
    double v[5];
    #pragma unroll
    for (int i = 0; i < 5; ++i)
        v[i] = g_acc2[i * NBUCKET + l] + g_acc2[i * NBUCKET + 32 + l];
    #pragma unroll
    for (int i = 0; i < 5; ++i)
        #pragma unroll
        for (int off = 16; off; off >>= 1)
            v[i] += __shfl_down_sync(0xFFFFFFFFu, v[i], off);
    if (l == 0) {
        double nact = v[1] > 1.0 ? v[1] : 1.0;
        double nfg  = v[2] > 1.0 ? v[2] : 1.0;
        out[0] = (float)(v[0] / nact + v[3] / nfg + v[4] / nfg);
    }
}

extern "C" void kernel_launch(void* const* d_in, const int* in_sizes, int n_in,
                              void* d_out, int out_size) {
    const float* cls  = (const float*)d_in[0];
    const float* b2   = (const float*)d_in[1];
    const float* b3   = (const float*)d_in[2];
    const float* gtb  = (const float*)d_in[3];
    const float* gt3  = (const float*)d_in[4];
    const int*   glbl = (const int*)d_in[5];
    const int*   gval = (const int*)d_in[6];
    const float* anc  = (const float*)d_in[7];
    const float* mn   = (const float*)d_in[8];
    const float* sd   = (const float*)d_in[9];
    float* out = (float*)d_out;

    k_init<<<1, 384>>>();
    k_assign<<<dim3(NA * FEAT_H, NB), 128>>>(gtb, gval, anc);
    k_force<<<1, NB * NG>>>(gval);
    k_loss<<<dim3(A_TOTAL / 256, NB), 256>>>(cls, b2, b3, gtb, gt3, glbl, anc, mn, sd);
    k_final<<<1, 32>>>(out);
}